// round 14
// baseline (speedup 1.0000x reference)
#include <cuda_runtime.h>
#include <cuda_fp16.h>
#include <cstdint>

#define NB 8
#define TQ 512
#define TKK 1024
#define NH 16
#define DH 64
#define DD 1024
// Q pre-scale: (H/D) * log2(e) folded into the Q projection output
#define QSCALE 0.02254211743f   // 0.015625 * 1.4426950408889634

// ---------------- device scratch (fp16) ----------------
__device__ __half g_qT[NB * TQ * DD];        // [n,t,c]
__device__ __half g_kvT[NB * TKK * DD];      // [n,t,c]
__device__ __half g_WqH[DD * DD];            // [d,c]
__device__ __half g_WkvH[2 * DD * DD];       // [d,c]
__device__ __half g_WfcH[DD * DD];           // [o,c]
__device__ __half g_QhH[NB * NH * TQ * DH];  // [n,h,t,e]  (pre-scaled by QSCALE)
__device__ __half g_KhH[NB * NH * TKK * DH]; // [n,h,k,e]
__device__ __half g_VtH[NB * NH * DH * TKK]; // [n,h,e,k]  (transposed V)
__device__ __half g_attOH[NB * TQ * DD];     // [n,t,d], d=h*64+e
__device__ uint32_t g_workCtr;               // persistent-attn work queue

#define ATTN_ITEMS (NB * NH * (TQ / 128))    // 512 work items
#define ATTN_GRID 296                        // 2 CTAs/SM x 148 SMs

// ---------------- helpers ----------------
#define MMA_F16(d, a0, a1, a2, a3, b0, b1)                                    \
    asm volatile(                                                             \
        "mma.sync.aligned.m16n8k16.row.col.f32.f16.f16.f32 "                  \
        "{%0,%1,%2,%3}, {%4,%5,%6,%7}, {%8,%9}, {%0,%1,%2,%3};\n"             \
        : "+f"(d[0]), "+f"(d[1]), "+f"(d[2]), "+f"(d[3])                      \
        : "r"(a0), "r"(a1), "r"(a2), "r"(a3), "r"(b0), "r"(b1))

__device__ __forceinline__ void ldsm_x4(uint32_t& r0, uint32_t& r1,
                                        uint32_t& r2, uint32_t& r3,
                                        uint32_t addr) {
    asm volatile("ldmatrix.sync.aligned.m8n8.x4.shared.b16 {%0,%1,%2,%3}, [%4];"
                 : "=r"(r0), "=r"(r1), "=r"(r2), "=r"(r3) : "r"(addr));
}

__device__ __forceinline__ void cp16(uint32_t dst, const void* src) {
    asm volatile("cp.async.cg.shared.global [%0], [%1], 16;\n" ::"r"(dst), "l"(src));
}
#define CP_COMMIT() asm volatile("cp.async.commit_group;\n" ::)
#define CP_WAIT1()  asm volatile("cp.async.wait_group 1;\n" ::)
#define CP_WAIT0()  asm volatile("cp.async.wait_group 0;\n" ::)

__device__ __forceinline__ uint32_t packh2(float lo, float hi) {
    __half2 h = __floats2half2_rn(lo, hi);
    return *reinterpret_cast<uint32_t*>(&h);
}

__device__ __forceinline__ float ex2f(float x) {
    float r;
    asm("ex2.approx.f32 %0, %1;" : "=f"(r) : "f"(x));
    return r;
}

// =========================================================================
// merged transpose + convert: q and kv in one launch.
// =========================================================================
__global__ __launch_bounds__(256) void transpose_all(
    const float* __restrict__ q, const float* __restrict__ kv) {
    __shared__ float tile[32][33];
    const int z = blockIdx.z;
    const bool isQ = z < NB;
    const int TD = isQ ? TQ : TKK;
    if (isQ && blockIdx.x >= TQ / 32) return;
    const int nb = isQ ? z : z - NB;
    const int c0 = blockIdx.y * 32, t0 = blockIdx.x * 32;
    const float* s = (isQ ? q : kv) + (size_t)nb * DD * TD;
    __half* d = (isQ ? g_qT : g_kvT) + (size_t)nb * TD * DD;
    const int tx = threadIdx.x & 31, ty = threadIdx.x >> 5;
#pragma unroll
    for (int i = 0; i < 4; i++)
        tile[ty + 8 * i][tx] = s[(size_t)(c0 + ty + 8 * i) * TD + t0 + tx];
    __syncthreads();
#pragma unroll
    for (int i = 0; i < 4; i++)
        d[(size_t)(t0 + ty + 8 * i) * DD + c0 + tx] =
            __float2half_rn(tile[tx][ty + 8 * i]);
}

// fused fp32 -> fp16 convert of Wq | Wkv | Wfc + work-counter reset
__global__ void convert_all(const float* __restrict__ Wq,
                            const float* __restrict__ Wkv,
                            const float* __restrict__ Wfc) {
    if (blockIdx.x == 0 && threadIdx.x == 0) g_workCtr = 0;
    const int N1 = DD * DD / 4;
    const int N2 = N1 + 2 * DD * DD / 4;
    const int NT = N2 + DD * DD / 4;
    int i = blockIdx.x * blockDim.x + threadIdx.x;
    if (i >= NT) return;
    const float* s;
    __half* d;
    int j;
    if (i < N1)       { s = Wq;  d = g_WqH;  j = i; }
    else if (i < N2)  { s = Wkv; d = g_WkvH; j = i - N1; }
    else              { s = Wfc; d = g_WfcH; j = i - N2; }
    float4 v = ((const float4*)s)[j];
    __half2* dd = (__half2*)d + j * 2;
    dd[0] = __floats2half2_rn(v.x, v.y);
    dd[1] = __floats2half2_rn(v.z, v.w);
}

// =========================================================================
// Shared GEMM mainloop: 128x128 block, BK=64/stage, 3-stage cp.async,
// one __syncthreads per stage. 256 thr = 8 warps (2m x 4n), warp tile 64x32.
// =========================================================================
#define HP2 36                       // smem row pitch in words (144 B)
#define H2TILE_B (128 * HP2 * 4)     // 18432 B per tile
#define H2STG_B  (2 * H2TILE_B)      // 36864 B per stage
#define HGEMM_SMEM (3 * H2STG_B)     // 110592 B

__device__ __forceinline__ void gemm_mainloop(
    const __half* __restrict__ Asrc, const __half* __restrict__ Bsrc,
    uint32_t sbase, int m0, int n0, int tid, int warp_m, int warp_n,
    uint32_t aOff, uint32_t bOff, float acc[4][4][4]) {

    auto issue = [&](int s, int kc) {
        const uint32_t stA = sbase + s * H2STG_B;
        const uint32_t stB = stA + H2TILE_B;
#pragma unroll
        for (int u = 0; u < 4; u++) {
            int ca = u * 256 + tid;
            int r = ca >> 3, ch = ca & 7;
            uint32_t soff = (r * HP2 + ch * 4) * 4;
            cp16(stA + soff, Asrc + (size_t)(m0 + r) * DD + kc * 64 + ch * 8);
            cp16(stB + soff, Bsrc + (size_t)(n0 + r) * DD + kc * 64 + ch * 8);
        }
    };

    issue(0, 0); CP_COMMIT();
    issue(1, 1); CP_COMMIT();

    const int KB = DD / 64;   // 16
    for (int kb = 0; kb < KB; kb++) {
        if (kb + 1 < KB) { CP_WAIT1(); } else { CP_WAIT0(); }
        __syncthreads();
        if (kb + 2 < KB) { issue((kb + 2) % 3, kb + 2); CP_COMMIT(); }

        const uint32_t stA = sbase + (kb % 3) * H2STG_B;
        const uint32_t stB = stA + H2TILE_B;
#pragma unroll
        for (int ks = 0; ks < 4; ks++) {
            const int kw = ks * 8;
            uint32_t a[4][4];
#pragma unroll
            for (int mt = 0; mt < 4; mt++)
                ldsm_x4(a[mt][0], a[mt][1], a[mt][2], a[mt][3],
                        stA + ((warp_m * 64 + mt * 16) * HP2 + kw) * 4 + aOff);
            uint32_t b[4][2];
#pragma unroll
            for (int np = 0; np < 2; np++)
                ldsm_x4(b[2 * np][0], b[2 * np][1], b[2 * np + 1][0], b[2 * np + 1][1],
                        stB + ((warp_n * 32 + np * 16) * HP2 + kw) * 4 + bOff);
#pragma unroll
            for (int nt = 0; nt < 4; nt++)
#pragma unroll
                for (int mt = 0; mt < 4; mt++)
                    MMA_F16(acc[mt][nt], a[mt][0], a[mt][1], a[mt][2], a[mt][3],
                            b[nt][0], b[nt][1]);
        }
    }
}

// =========================================================================
// Merged projection kernel: grid.x = 160 tiles (32 Q + 128 KV), grid.z = NB.
// =========================================================================
__global__ __launch_bounds__(256, 2) void proj_all(
    const float* __restrict__ bq, const float* __restrict__ bkv) {
    extern __shared__ uint32_t sw[];
    const uint32_t sbase = (uint32_t)__cvta_generic_to_shared(sw);

    const int nb = blockIdx.z;
    const int bx = blockIdx.x;
    const int tid = threadIdx.x;
    const int lane = tid & 31, wid = tid >> 5;
    const int gr = lane >> 2, tig = lane & 3;
    const int warp_m = wid & 1, warp_n = wid >> 1;

    const uint32_t aOff = ((lane & 15) * HP2 + ((lane >> 4) & 1) * 4) * 4;
    const uint32_t bOff =
        (((lane & 7) + ((lane >> 4) & 1) * 8) * HP2 + ((lane >> 3) & 1) * 4) * 4;

    int mode, m0, n0;
    const __half *Asrc, *Bsrc;
    const float* bias;
    if (bx < 32) {
        mode = 0;
        m0 = (bx & 3) * 128;
        n0 = (bx >> 2) * 128;
        Asrc = g_qT + (size_t)nb * TQ * DD;
        Bsrc = g_WqH;
        bias = bq;
    } else {
        mode = 1;
        int kx = bx - 32;
        m0 = (kx & 7) * 128;
        n0 = (kx >> 3) * 128;
        Asrc = g_kvT + (size_t)nb * TKK * DD;
        Bsrc = g_WkvH;
        bias = bkv;
    }

    float acc[4][4][4];
#pragma unroll
    for (int mt = 0; mt < 4; mt++)
#pragma unroll
        for (int nt = 0; nt < 4; nt++)
#pragma unroll
            for (int i = 0; i < 4; i++) acc[mt][nt][i] = 0.f;

    gemm_mainloop(Asrc, Bsrc, sbase, m0, n0, tid, warp_m, warp_n, aOff, bOff, acc);

    // ---- epilogue ----
#pragma unroll
    for (int mt = 0; mt < 4; mt++) {
        int row = m0 + warp_m * 64 + mt * 16 + gr;
#pragma unroll
        for (int nt = 0; nt < 4; nt++) {
            int col = n0 + warp_n * 32 + nt * 8 + 2 * tig;
            float2 bv = *(const float2*)(bias + col);
            float v0 = acc[mt][nt][0] + bv.x, v1 = acc[mt][nt][1] + bv.y;
            float v2 = acc[mt][nt][2] + bv.x, v3 = acc[mt][nt][3] + bv.y;
            if (mode == 0) {
                v0 *= QSCALE; v1 *= QSCALE; v2 *= QSCALE; v3 *= QSCALE;
                int h = col >> 6, e = col & 63;
                __half* dst = g_QhH + ((size_t)(nb * NH + h) * TQ + row) * DH + e;
                *(__half2*)dst = __floats2half2_rn(v0, v1);
                *(__half2*)(dst + 8 * DH) = __floats2half2_rn(v2, v3);
            } else {
                int h = col >> 7, e = col & 127;
                if (e < 64) {
                    __half* dst = g_KhH + ((size_t)(nb * NH + h) * TKK + row) * DH + e;
                    *(__half2*)dst = __floats2half2_rn(v0, v1);
                    *(__half2*)(dst + 8 * DH) = __floats2half2_rn(v2, v3);
                } else {
                    int ee = e - 64;
                    __half* hb = g_VtH + ((size_t)(nb * NH + h) * DH + ee) * TKK;
                    hb[row] = __float2half_rn(v0);
                    hb[TKK + row] = __float2half_rn(v1);
                    hb[row + 8] = __float2half_rn(v2);
                    hb[TKK + row + 8] = __float2half_rn(v3);
                }
            }
        }
    }
}

// =========================================================================
// FC kernel: out[n,o,t] = Wfc @ attO^T + bfc
// =========================================================================
__global__ __launch_bounds__(256, 2) void fc_gemm(
    const float* __restrict__ bias, float* __restrict__ out) {
    extern __shared__ uint32_t sw[];
    const uint32_t sbase = (uint32_t)__cvta_generic_to_shared(sw);

    const int nb = blockIdx.z;
    const int m0 = blockIdx.x * 128;
    const int n0 = blockIdx.y * 128;
    const int tid = threadIdx.x;
    const int lane = tid & 31, wid = tid >> 5;
    const int gr = lane >> 2, tig = lane & 3;
    const int warp_m = wid & 1, warp_n = wid >> 1;

    const uint32_t aOff = ((lane & 15) * HP2 + ((lane >> 4) & 1) * 4) * 4;
    const uint32_t bOff =
        (((lane & 7) + ((lane >> 4) & 1) * 8) * HP2 + ((lane >> 3) & 1) * 4) * 4;

    float acc[4][4][4];
#pragma unroll
    for (int mt = 0; mt < 4; mt++)
#pragma unroll
        for (int nt = 0; nt < 4; nt++)
#pragma unroll
            for (int i = 0; i < 4; i++) acc[mt][nt][i] = 0.f;

    gemm_mainloop(g_WfcH, g_attOH + (size_t)nb * TQ * DD,
                  sbase, m0, n0, tid, warp_m, warp_n, aOff, bOff, acc);

#pragma unroll
    for (int mt = 0; mt < 4; mt++) {
        int row = m0 + warp_m * 64 + mt * 16 + gr;
        float b0v = bias[row], b8v = bias[row + 8];
#pragma unroll
        for (int nt = 0; nt < 4; nt++) {
            int col = n0 + warp_n * 32 + nt * 8 + 2 * tig;
            float* o0 = out + ((size_t)nb * DD + row) * TQ + col;
            *(float2*)o0 = make_float2(acc[mt][nt][0] + b0v, acc[mt][nt][1] + b0v);
            *(float2*)(o0 + (size_t)8 * TQ) =
                make_float2(acc[mt][nt][2] + b8v, acc[mt][nt][3] + b8v);
        }
    }
}

// =========================================================================
// Persistent fp16 flash attention, base-2 softmax. 296 CTAs grab work items
// (bh, t0) from g_workCtr. Br=128, Bc=64, 256 thr = 8 warps x 16 q-rows.
// =========================================================================
#define AP 36
#define KV_STG_W (128 * AP)
#define ATTN_SMEM ((128 * AP + 2 * KV_STG_W) * 4)   // 55296 B

__global__ __launch_bounds__(256, 2) void attn_h(const int* __restrict__ kv_len) {
    extern __shared__ uint32_t sw[];
    __shared__ uint32_t s_idx;
    const uint32_t sbase = (uint32_t)__cvta_generic_to_shared(sw);
    uint32_t* Qs = sw;

    const int tid = threadIdx.x;
    const int w = tid >> 5, lane = tid & 31;
    const int gr = lane >> 2, tig = lane & 3;
    const int rb = w * 16;

    const uint32_t aOff = ((lane & 15) * AP + ((lane >> 4) & 1) * 4) * 4;
    const uint32_t bOff =
        (((lane & 7) + ((lane >> 4) & 1) * 8) * AP + ((lane >> 3) & 1) * 4) * 4;

    while (true) {
        if (tid == 0) s_idx = atomicAdd(&g_workCtr, 1u);
        __syncthreads();   // broadcast idx; also orders stage-buffer reuse
        const uint32_t idx = s_idx;
        if (idx >= ATTN_ITEMS) break;

        const int bh = idx >> 2;           // n*16 + h  (consecutive grabs share bh)
        const int t0 = (idx & 3) * 128;
        const int nb = bh >> 4;
        const int len = kv_len[nb];

        const __half* Qg = g_QhH + ((size_t)bh * TQ + t0) * DH;
        const __half* Kg = g_KhH + (size_t)bh * TKK * DH;
        const __half* Vt = g_VtH + (size_t)bh * DH * TKK;

        // Q tile
#pragma unroll
        for (int u = 0; u < 4; u++) {
            int lin = tid + u * 256;
            int row = lin >> 3, ch = lin & 7;
            uint4 v = *(const uint4*)(Qg + (size_t)row * DH + ch * 8);
            *(uint4*)(Qs + row * AP + ch * 4) = v;
        }

        auto issueKV = [&](int kt, int s) {
            const uint32_t stK = sbase + (128 * AP + s * KV_STG_W) * 4;
            const uint32_t stV = stK + 64 * AP * 4;
            const int k0 = kt * 64;
#pragma unroll
            for (int u = 0; u < 2; u++) {
                int lin = tid + u * 256;
                int row = lin >> 3, ch = lin & 7;
                cp16(stK + (row * AP + ch * 4) * 4,
                     Kg + (size_t)(k0 + row) * DH + ch * 8);
                cp16(stV + (row * AP + ch * 4) * 4,
                     Vt + (size_t)row * TKK + k0 + ch * 8);
            }
        };

        float m[2], l[2], oacc[8][4];
        m[0] = m[1] = -1e30f;
        l[0] = l[1] = 0.f;
#pragma unroll
        for (int nt = 0; nt < 8; nt++)
#pragma unroll
            for (int i = 0; i < 4; i++) oacc[nt][i] = 0.f;

        const int ktiles = (len + 63) >> 6;
        issueKV(0, 0); CP_COMMIT();

        for (int kt = 0; kt < ktiles; kt++) {
            const int k0 = kt * 64;
            const int st = kt & 1;
            CP_WAIT0();
            __syncthreads();
            if (kt + 1 < ktiles) { issueKV(kt + 1, st ^ 1); CP_COMMIT(); }

            const uint32_t stK = sbase + (128 * AP + st * KV_STG_W) * 4;
            const uint32_t stV = stK + 64 * AP * 4;

            // ---- S = Q @ K^T (log2 units) ----
            float sacc[8][4];
#pragma unroll
            for (int nt = 0; nt < 8; nt++)
#pragma unroll
                for (int i = 0; i < 4; i++) sacc[nt][i] = 0.f;

#pragma unroll
            for (int es = 0; es < 4; es++) {
                const int ew = es * 8;
                uint32_t a0, a1, a2, a3;
                ldsm_x4(a0, a1, a2, a3, sbase + (rb * AP + ew) * 4 + aOff);
                uint32_t b[8][2];
#pragma unroll
                for (int np = 0; np < 4; np++)
                    ldsm_x4(b[2 * np][0], b[2 * np][1], b[2 * np + 1][0], b[2 * np + 1][1],
                            stK + (np * 16 * AP + ew) * 4 + bOff);
#pragma unroll
                for (int nt = 0; nt < 8; nt++)
                    MMA_F16(sacc[nt], a0, a1, a2, a3, b[nt][0], b[nt][1]);
            }

            // ---- online softmax (base 2) ----
            if (k0 + 64 > len) {
#pragma unroll
                for (int nt = 0; nt < 8; nt++)
#pragma unroll
                    for (int i = 0; i < 4; i++) {
                        int col = k0 + nt * 8 + 2 * tig + (i & 1);
                        if (col >= len) sacc[nt][i] = -1e30f;
                    }
            }
#pragma unroll
            for (int rr = 0; rr < 2; rr++) {
                float mx = -1e30f;
#pragma unroll
                for (int nt = 0; nt < 8; nt++)
                    mx = fmaxf(mx, fmaxf(sacc[nt][rr * 2], sacc[nt][rr * 2 + 1]));
                mx = fmaxf(mx, __shfl_xor_sync(0xffffffffu, mx, 1));
                mx = fmaxf(mx, __shfl_xor_sync(0xffffffffu, mx, 2));
                float mn = fmaxf(m[rr], mx);
                float sf = ex2f(m[rr] - mn);
                m[rr] = mn;
                float sum = 0.f;
#pragma unroll
                for (int nt = 0; nt < 8; nt++)
#pragma unroll
                    for (int cc = 0; cc < 2; cc++) {
                        float p = ex2f(sacc[nt][rr * 2 + cc] - mn);
                        sacc[nt][rr * 2 + cc] = p;
                        sum += p;
                    }
                sum += __shfl_xor_sync(0xffffffffu, sum, 1);
                sum += __shfl_xor_sync(0xffffffffu, sum, 2);
                l[rr] = l[rr] * sf + sum;
#pragma unroll
                for (int nt = 0; nt < 8; nt++)
#pragma unroll
                    for (int cc = 0; cc < 2; cc++) oacc[nt][rr * 2 + cc] *= sf;
            }

            // ---- O += P @ V (P via registers) ----
#pragma unroll
            for (int js = 0; js < 4; js++) {
                uint32_t pa0 = packh2(sacc[2 * js][0], sacc[2 * js][1]);
                uint32_t pa1 = packh2(sacc[2 * js][2], sacc[2 * js][3]);
                uint32_t pa2 = packh2(sacc[2 * js + 1][0], sacc[2 * js + 1][1]);
                uint32_t pa3 = packh2(sacc[2 * js + 1][2], sacc[2 * js + 1][3]);
                uint32_t b[8][2];
#pragma unroll
                for (int np = 0; np < 4; np++)
                    ldsm_x4(b[2 * np][0], b[2 * np][1], b[2 * np + 1][0], b[2 * np + 1][1],
                            stV + (np * 16 * AP + js * 8) * 4 + bOff);
#pragma unroll
                for (int nt = 0; nt < 8; nt++)
                    MMA_F16(oacc[nt], pa0, pa1, pa2, pa3, b[nt][0], b[nt][1]);
            }
        }

        // ---- normalize + store ----
        const int h = bh & 15;
        const int nb2 = bh >> 4;
        float inv0 = 1.0f / l[0];
        float inv1 = 1.0f / l[1];
        int r0 = t0 + rb + gr;
        __half* dst = g_attOH + ((size_t)nb2 * TQ + r0) * DD + h * DH;
#pragma unroll
        for (int nt = 0; nt < 8; nt++) {
            int col = nt * 8 + 2 * tig;
            *(__half2*)(dst + col) =
                __floats2half2_rn(oacc[nt][0] * inv0, oacc[nt][1] * inv0);
            *(__half2*)(dst + (size_t)8 * DD + col) =
                __floats2half2_rn(oacc[nt][2] * inv1, oacc[nt][3] * inv1);
        }
    }
}

// =========================================================================
extern "C" void kernel_launch(void* const* d_in, const int* in_sizes, int n_in,
                              void* d_out, int out_size) {
    const float* q   = (const float*)d_in[0];
    const float* kv  = (const float*)d_in[1];
    const int*   kvl = (const int*)d_in[2];
    const float* Wq  = (const float*)d_in[3];
    const float* bq  = (const float*)d_in[4];
    const float* Wkv = (const float*)d_in[5];
    const float* bkv = (const float*)d_in[6];
    const float* Wfc = (const float*)d_in[7];
    const float* bfc = (const float*)d_in[8];
    float* out = (float*)d_out;

    cudaFuncSetAttribute(proj_all, cudaFuncAttributeMaxDynamicSharedMemorySize, HGEMM_SMEM);
    cudaFuncSetAttribute(fc_gemm, cudaFuncAttributeMaxDynamicSharedMemorySize, HGEMM_SMEM);
    cudaFuncSetAttribute(attn_h, cudaFuncAttributeMaxDynamicSharedMemorySize, ATTN_SMEM);

    // 1. merged transposes + fused weight convert (also resets work counter)
    transpose_all<<<dim3(TKK / 32, DD / 32, 2 * NB), 256>>>(q, kv);
    convert_all<<<(DD * DD + 255) / 256, 256>>>(Wq, Wkv, Wfc);

    // 2. merged projections
    proj_all<<<dim3(160, 1, NB), 256, HGEMM_SMEM>>>(bq, bkv);
    // 3. persistent attention
    attn_h<<<ATTN_GRID, 256, ATTN_SMEM>>>(kvl);
    // 4. fc
    fc_gemm<<<dim3(DD / 128, TQ / 128, NB), 256, HGEMM_SMEM>>>(bfc, out);
}

// round 15
// speedup vs baseline: 1.0168x; 1.0168x over previous
#include <cuda_runtime.h>
#include <cuda_fp16.h>
#include <cstdint>

#define NB 8
#define TQ 512
#define TKK 1024
#define NH 16
#define DH 64
#define DD 1024
// Q pre-scale: (H/D) * log2(e) folded into the Q projection output
#define QSCALE 0.02254211743f   // 0.015625 * 1.4426950408889634

// ---------------- device scratch (fp16) ----------------
__device__ __half g_qT[NB * TQ * DD];        // [n,t,c]
__device__ __half g_kvT[NB * TKK * DD];      // [n,t,c]
__device__ __half g_WqH[DD * DD];            // [d,c]
__device__ __half g_WkvH[2 * DD * DD];       // [d,c]
__device__ __half g_WfcH[DD * DD];           // [o,c]
__device__ __half g_QhH[NB * NH * TQ * DH];  // [n,h,t,e]  (pre-scaled by QSCALE)
__device__ __half g_KhH[NB * NH * TKK * DH]; // [n,h,k,e]
__device__ __half g_VtH[NB * NH * DH * TKK]; // [n,h,e,k]  (transposed V)
__device__ __half g_attOH[NB * TQ * DD];     // [n,t,d], d=h*64+e

// ---------------- helpers ----------------
#define MMA_F16(d, a0, a1, a2, a3, b0, b1)                                    \
    asm volatile(                                                             \
        "mma.sync.aligned.m16n8k16.row.col.f32.f16.f16.f32 "                  \
        "{%0,%1,%2,%3}, {%4,%5,%6,%7}, {%8,%9}, {%0,%1,%2,%3};\n"             \
        : "+f"(d[0]), "+f"(d[1]), "+f"(d[2]), "+f"(d[3])                      \
        : "r"(a0), "r"(a1), "r"(a2), "r"(a3), "r"(b0), "r"(b1))

__device__ __forceinline__ void ldsm_x4(uint32_t& r0, uint32_t& r1,
                                        uint32_t& r2, uint32_t& r3,
                                        uint32_t addr) {
    asm volatile("ldmatrix.sync.aligned.m8n8.x4.shared.b16 {%0,%1,%2,%3}, [%4];"
                 : "=r"(r0), "=r"(r1), "=r"(r2), "=r"(r3) : "r"(addr));
}

__device__ __forceinline__ void cp16(uint32_t dst, const void* src) {
    asm volatile("cp.async.cg.shared.global [%0], [%1], 16;\n" ::"r"(dst), "l"(src));
}
#define CP_COMMIT() asm volatile("cp.async.commit_group;\n" ::)
#define CP_WAIT1()  asm volatile("cp.async.wait_group 1;\n" ::)
#define CP_WAIT0()  asm volatile("cp.async.wait_group 0;\n" ::)

__device__ __forceinline__ uint32_t packh2(float lo, float hi) {
    __half2 h = __floats2half2_rn(lo, hi);
    return *reinterpret_cast<uint32_t*>(&h);
}

__device__ __forceinline__ float ex2f(float x) {
    float r;
    asm("ex2.approx.f32 %0, %1;" : "=f"(r) : "f"(x));
    return r;
}

// =========================================================================
// merged transpose + convert: q and kv in one launch.
// =========================================================================
__global__ __launch_bounds__(256) void transpose_all(
    const float* __restrict__ q, const float* __restrict__ kv) {
    __shared__ float tile[32][33];
    const int z = blockIdx.z;
    const bool isQ = z < NB;
    const int TD = isQ ? TQ : TKK;
    if (isQ && blockIdx.x >= TQ / 32) return;
    const int nb = isQ ? z : z - NB;
    const int c0 = blockIdx.y * 32, t0 = blockIdx.x * 32;
    const float* s = (isQ ? q : kv) + (size_t)nb * DD * TD;
    __half* d = (isQ ? g_qT : g_kvT) + (size_t)nb * TD * DD;
    const int tx = threadIdx.x & 31, ty = threadIdx.x >> 5;
#pragma unroll
    for (int i = 0; i < 4; i++)
        tile[ty + 8 * i][tx] = s[(size_t)(c0 + ty + 8 * i) * TD + t0 + tx];
    __syncthreads();
#pragma unroll
    for (int i = 0; i < 4; i++)
        d[(size_t)(t0 + ty + 8 * i) * DD + c0 + tx] =
            __float2half_rn(tile[tx][ty + 8 * i]);
}

// fused fp32 -> fp16 convert of Wq | Wkv | Wfc (one launch)
__global__ void convert_all(const float* __restrict__ Wq,
                            const float* __restrict__ Wkv,
                            const float* __restrict__ Wfc) {
    const int N1 = DD * DD / 4;
    const int N2 = N1 + 2 * DD * DD / 4;
    const int NT = N2 + DD * DD / 4;
    int i = blockIdx.x * blockDim.x + threadIdx.x;
    if (i >= NT) return;
    const float* s;
    __half* d;
    int j;
    if (i < N1)       { s = Wq;  d = g_WqH;  j = i; }
    else if (i < N2)  { s = Wkv; d = g_WkvH; j = i - N1; }
    else              { s = Wfc; d = g_WfcH; j = i - N2; }
    float4 v = ((const float4*)s)[j];
    __half2* dd = (__half2*)d + j * 2;
    dd[0] = __floats2half2_rn(v.x, v.y);
    dd[1] = __floats2half2_rn(v.z, v.w);
}

// =========================================================================
// Shared GEMM mainloop: 128x128 block, BK=64/stage, 3-stage cp.async,
// one __syncthreads per stage. 256 thr = 8 warps (2m x 4n), warp tile 64x32.
// =========================================================================
#define HP2 36                       // smem row pitch in words (144 B)
#define H2TILE_B (128 * HP2 * 4)     // 18432 B per tile
#define H2STG_B  (2 * H2TILE_B)      // 36864 B per stage
#define HGEMM_SMEM (3 * H2STG_B)     // 110592 B

__device__ __forceinline__ void gemm_mainloop(
    const __half* __restrict__ Asrc, const __half* __restrict__ Bsrc,
    uint32_t sbase, int m0, int n0, int tid, int warp_m, int warp_n,
    uint32_t aOff, uint32_t bOff, float acc[4][4][4]) {

    auto issue = [&](int s, int kc) {
        const uint32_t stA = sbase + s * H2STG_B;
        const uint32_t stB = stA + H2TILE_B;
#pragma unroll
        for (int u = 0; u < 4; u++) {
            int ca = u * 256 + tid;
            int r = ca >> 3, ch = ca & 7;
            uint32_t soff = (r * HP2 + ch * 4) * 4;
            cp16(stA + soff, Asrc + (size_t)(m0 + r) * DD + kc * 64 + ch * 8);
            cp16(stB + soff, Bsrc + (size_t)(n0 + r) * DD + kc * 64 + ch * 8);
        }
    };

    issue(0, 0); CP_COMMIT();
    issue(1, 1); CP_COMMIT();

    const int KB = DD / 64;   // 16
    for (int kb = 0; kb < KB; kb++) {
        if (kb + 1 < KB) { CP_WAIT1(); } else { CP_WAIT0(); }
        __syncthreads();
        if (kb + 2 < KB) { issue((kb + 2) % 3, kb + 2); CP_COMMIT(); }

        const uint32_t stA = sbase + (kb % 3) * H2STG_B;
        const uint32_t stB = stA + H2TILE_B;
#pragma unroll
        for (int ks = 0; ks < 4; ks++) {
            const int kw = ks * 8;
            uint32_t a[4][4];
#pragma unroll
            for (int mt = 0; mt < 4; mt++)
                ldsm_x4(a[mt][0], a[mt][1], a[mt][2], a[mt][3],
                        stA + ((warp_m * 64 + mt * 16) * HP2 + kw) * 4 + aOff);
            uint32_t b[4][2];
#pragma unroll
            for (int np = 0; np < 2; np++)
                ldsm_x4(b[2 * np][0], b[2 * np][1], b[2 * np + 1][0], b[2 * np + 1][1],
                        stB + ((warp_n * 32 + np * 16) * HP2 + kw) * 4 + bOff);
#pragma unroll
            for (int nt = 0; nt < 4; nt++)
#pragma unroll
                for (int mt = 0; mt < 4; mt++)
                    MMA_F16(acc[mt][nt], a[mt][0], a[mt][1], a[mt][2], a[mt][3],
                            b[nt][0], b[nt][1]);
        }
    }
}

// =========================================================================
// Merged projection kernel: grid.x = 160 tiles (32 Q + 128 KV), grid.z = NB.
// Q output pre-scaled by QSCALE. KV n-tile == one head (K|V split at e=64);
// V half is staged through smem for coalesced transposed stores.
// =========================================================================
__global__ __launch_bounds__(256, 2) void proj_all(
    const float* __restrict__ bq, const float* __restrict__ bkv) {
    extern __shared__ uint32_t sw[];
    const uint32_t sbase = (uint32_t)__cvta_generic_to_shared(sw);

    const int nb = blockIdx.z;
    const int bx = blockIdx.x;
    const int tid = threadIdx.x;
    const int lane = tid & 31, wid = tid >> 5;
    const int gr = lane >> 2, tig = lane & 3;
    const int warp_m = wid & 1, warp_n = wid >> 1;

    const uint32_t aOff = ((lane & 15) * HP2 + ((lane >> 4) & 1) * 4) * 4;
    const uint32_t bOff =
        (((lane & 7) + ((lane >> 4) & 1) * 8) * HP2 + ((lane >> 3) & 1) * 4) * 4;

    int mode, m0, n0;
    const __half *Asrc, *Bsrc;
    const float* bias;
    if (bx < 32) {
        mode = 0;
        m0 = (bx & 3) * 128;
        n0 = (bx >> 2) * 128;
        Asrc = g_qT + (size_t)nb * TQ * DD;
        Bsrc = g_WqH;
        bias = bq;
    } else {
        mode = 1;
        int kx = bx - 32;
        m0 = (kx & 7) * 128;
        n0 = (kx >> 3) * 128;
        Asrc = g_kvT + (size_t)nb * TKK * DD;
        Bsrc = g_WkvH;
        bias = bkv;
    }

    float acc[4][4][4];
#pragma unroll
    for (int mt = 0; mt < 4; mt++)
#pragma unroll
        for (int nt = 0; nt < 4; nt++)
#pragma unroll
            for (int i = 0; i < 4; i++) acc[mt][nt][i] = 0.f;

    gemm_mainloop(Asrc, Bsrc, sbase, m0, n0, tid, warp_m, warp_n, aOff, bOff, acc);

    if (mode == 0) {
        // ---- Q epilogue: direct coalesced stores ----
#pragma unroll
        for (int mt = 0; mt < 4; mt++) {
            int row = m0 + warp_m * 64 + mt * 16 + gr;
#pragma unroll
            for (int nt = 0; nt < 4; nt++) {
                int col = n0 + warp_n * 32 + nt * 8 + 2 * tig;
                float2 bv = *(const float2*)(bias + col);
                float v0 = (acc[mt][nt][0] + bv.x) * QSCALE;
                float v1 = (acc[mt][nt][1] + bv.y) * QSCALE;
                float v2 = (acc[mt][nt][2] + bv.x) * QSCALE;
                float v3 = (acc[mt][nt][3] + bv.y) * QSCALE;
                int h = col >> 6, e = col & 63;
                __half* dst = g_QhH + ((size_t)(nb * NH + h) * TQ + row) * DH + e;
                *(__half2*)dst = __floats2half2_rn(v0, v1);
                *(__half2*)(dst + 8 * DH) = __floats2half2_rn(v2, v3);
            }
        }
    } else {
        // ---- KV epilogue: K direct, V staged through smem ----
        const int h = n0 >> 7;
        __syncthreads();   // mainloop smem reads done; reuse stage 0 as Vst
        __half* Vst = (__half*)sw;   // [e(64)][m(128)]
#pragma unroll
        for (int mt = 0; mt < 4; mt++) {
            int rl = warp_m * 64 + mt * 16 + gr;   // local row 0..127
            int row = m0 + rl;
#pragma unroll
            for (int nt = 0; nt < 4; nt++) {
                int col = n0 + warp_n * 32 + nt * 8 + 2 * tig;
                float2 bv = *(const float2*)(bias + col);
                float v0 = acc[mt][nt][0] + bv.x, v1 = acc[mt][nt][1] + bv.y;
                float v2 = acc[mt][nt][2] + bv.x, v3 = acc[mt][nt][3] + bv.y;
                int e = col & 127;
                if (e < 64) {
                    __half* dst = g_KhH + ((size_t)(nb * NH + h) * TKK + row) * DH + e;
                    *(__half2*)dst = __floats2half2_rn(v0, v1);
                    *(__half2*)(dst + 8 * DH) = __floats2half2_rn(v2, v3);
                } else {
                    int ee = e - 64;
                    Vst[ee * 128 + rl] = __float2half_rn(v0);
                    Vst[(ee + 1) * 128 + rl] = __float2half_rn(v1);
                    Vst[ee * 128 + rl + 8] = __float2half_rn(v2);
                    Vst[(ee + 1) * 128 + rl + 8] = __float2half_rn(v3);
                }
            }
        }
        __syncthreads();
        // cooperative coalesced store: 64 e-rows x 128 halves (256 B each)
        __half* vb = g_VtH + (size_t)(nb * NH + h) * DH * TKK;
#pragma unroll
        for (int u = 0; u < 4; u++) {
            int idx = u * 256 + tid;       // 0..1023
            int e = idx >> 4, ch = idx & 15;
            uint4 val = *(uint4*)(Vst + e * 128 + ch * 8);
            *(uint4*)(vb + (size_t)e * TKK + m0 + ch * 8) = val;
        }
    }
}

// =========================================================================
// FC kernel: out[n,o,t] = Wfc @ attO^T + bfc
// =========================================================================
__global__ __launch_bounds__(256, 2) void fc_gemm(
    const float* __restrict__ bias, float* __restrict__ out) {
    extern __shared__ uint32_t sw[];
    const uint32_t sbase = (uint32_t)__cvta_generic_to_shared(sw);

    const int nb = blockIdx.z;
    const int m0 = blockIdx.x * 128;
    const int n0 = blockIdx.y * 128;
    const int tid = threadIdx.x;
    const int lane = tid & 31, wid = tid >> 5;
    const int gr = lane >> 2, tig = lane & 3;
    const int warp_m = wid & 1, warp_n = wid >> 1;

    const uint32_t aOff = ((lane & 15) * HP2 + ((lane >> 4) & 1) * 4) * 4;
    const uint32_t bOff =
        (((lane & 7) + ((lane >> 4) & 1) * 8) * HP2 + ((lane >> 3) & 1) * 4) * 4;

    float acc[4][4][4];
#pragma unroll
    for (int mt = 0; mt < 4; mt++)
#pragma unroll
        for (int nt = 0; nt < 4; nt++)
#pragma unroll
            for (int i = 0; i < 4; i++) acc[mt][nt][i] = 0.f;

    gemm_mainloop(g_WfcH, g_attOH + (size_t)nb * TQ * DD,
                  sbase, m0, n0, tid, warp_m, warp_n, aOff, bOff, acc);

#pragma unroll
    for (int mt = 0; mt < 4; mt++) {
        int row = m0 + warp_m * 64 + mt * 16 + gr;
        float b0v = bias[row], b8v = bias[row + 8];
#pragma unroll
        for (int nt = 0; nt < 4; nt++) {
            int col = n0 + warp_n * 32 + nt * 8 + 2 * tig;
            float* o0 = out + ((size_t)nb * DD + row) * TQ + col;
            *(float2*)o0 = make_float2(acc[mt][nt][0] + b0v, acc[mt][nt][1] + b0v);
            *(float2*)(o0 + (size_t)8 * TQ) =
                make_float2(acc[mt][nt][2] + b8v, acc[mt][nt][3] + b8v);
        }
    }
}

// =========================================================================
// fp16 flash attention (round-13 version). Br=128, Bc=64, 256 thr = 8 warps.
// base-2 softmax, ex2.approx, interior-tile fast path, one barrier per tile.
// =========================================================================
#define AP 36
#define KV_STG_W (128 * AP)
#define ATTN_SMEM ((128 * AP + 2 * KV_STG_W) * 4)   // 55296 B

__global__ __launch_bounds__(256, 2) void attn_h(const int* __restrict__ kv_len) {
    extern __shared__ uint32_t sw[];
    const uint32_t sbase = (uint32_t)__cvta_generic_to_shared(sw);
    uint32_t* Qs = sw;

    const int bh = blockIdx.y;
    const int nb = bh >> 4;
    const int t0 = blockIdx.x * 128;
    const int len = kv_len[nb];

    const __half* Qg = g_QhH + ((size_t)bh * TQ + t0) * DH;
    const __half* Kg = g_KhH + (size_t)bh * TKK * DH;
    const __half* Vt = g_VtH + (size_t)bh * DH * TKK;

    const int tid = threadIdx.x;
    const int w = tid >> 5, lane = tid & 31;
    const int gr = lane >> 2, tig = lane & 3;
    const int rb = w * 16;

    const uint32_t aOff = ((lane & 15) * AP + ((lane >> 4) & 1) * 4) * 4;
    const uint32_t bOff =
        (((lane & 7) + ((lane >> 4) & 1) * 8) * AP + ((lane >> 3) & 1) * 4) * 4;

#pragma unroll
    for (int u = 0; u < 4; u++) {
        int lin = tid + u * 256;
        int row = lin >> 3, ch = lin & 7;
        uint4 v = *(const uint4*)(Qg + (size_t)row * DH + ch * 8);
        *(uint4*)(Qs + row * AP + ch * 4) = v;
    }

    auto issueKV = [&](int kt, int s) {
        const uint32_t stK = sbase + (128 * AP + s * KV_STG_W) * 4;
        const uint32_t stV = stK + 64 * AP * 4;
        const int k0 = kt * 64;
#pragma unroll
        for (int u = 0; u < 2; u++) {
            int lin = tid + u * 256;
            int row = lin >> 3, ch = lin & 7;
            cp16(stK + (row * AP + ch * 4) * 4,
                 Kg + (size_t)(k0 + row) * DH + ch * 8);
            cp16(stV + (row * AP + ch * 4) * 4,
                 Vt + (size_t)row * TKK + k0 + ch * 8);
        }
    };

    float m[2], l[2], oacc[8][4];
    m[0] = m[1] = -1e30f;
    l[0] = l[1] = 0.f;
#pragma unroll
    for (int nt = 0; nt < 8; nt++)
#pragma unroll
        for (int i = 0; i < 4; i++) oacc[nt][i] = 0.f;

    const int ktiles = (len + 63) >> 6;
    issueKV(0, 0); CP_COMMIT();

    for (int kt = 0; kt < ktiles; kt++) {
        const int k0 = kt * 64;
        const int st = kt & 1;
        CP_WAIT0();
        __syncthreads();
        if (kt + 1 < ktiles) { issueKV(kt + 1, st ^ 1); CP_COMMIT(); }

        const uint32_t stK = sbase + (128 * AP + st * KV_STG_W) * 4;
        const uint32_t stV = stK + 64 * AP * 4;

        // ---- S = Q @ K^T  (log2 units) ----
        float sacc[8][4];
#pragma unroll
        for (int nt = 0; nt < 8; nt++)
#pragma unroll
            for (int i = 0; i < 4; i++) sacc[nt][i] = 0.f;

#pragma unroll
        for (int es = 0; es < 4; es++) {
            const int ew = es * 8;
            uint32_t a0, a1, a2, a3;
            ldsm_x4(a0, a1, a2, a3, sbase + (rb * AP + ew) * 4 + aOff);
            uint32_t b[8][2];
#pragma unroll
            for (int np = 0; np < 4; np++)
                ldsm_x4(b[2 * np][0], b[2 * np][1], b[2 * np + 1][0], b[2 * np + 1][1],
                        stK + (np * 16 * AP + ew) * 4 + bOff);
#pragma unroll
            for (int nt = 0; nt < 8; nt++)
                MMA_F16(sacc[nt], a0, a1, a2, a3, b[nt][0], b[nt][1]);
        }

        // ---- online softmax (base 2) ----
        if (k0 + 64 > len) {
#pragma unroll
            for (int nt = 0; nt < 8; nt++)
#pragma unroll
                for (int i = 0; i < 4; i++) {
                    int col = k0 + nt * 8 + 2 * tig + (i & 1);
                    if (col >= len) sacc[nt][i] = -1e30f;
                }
        }
#pragma unroll
        for (int rr = 0; rr < 2; rr++) {
            float mx = -1e30f;
#pragma unroll
            for (int nt = 0; nt < 8; nt++)
                mx = fmaxf(mx, fmaxf(sacc[nt][rr * 2], sacc[nt][rr * 2 + 1]));
            mx = fmaxf(mx, __shfl_xor_sync(0xffffffffu, mx, 1));
            mx = fmaxf(mx, __shfl_xor_sync(0xffffffffu, mx, 2));
            float mn = fmaxf(m[rr], mx);
            float sf = ex2f(m[rr] - mn);
            m[rr] = mn;
            float sum = 0.f;
#pragma unroll
            for (int nt = 0; nt < 8; nt++)
#pragma unroll
                for (int cc = 0; cc < 2; cc++) {
                    float p = ex2f(sacc[nt][rr * 2 + cc] - mn);
                    sacc[nt][rr * 2 + cc] = p;
                    sum += p;
                }
            sum += __shfl_xor_sync(0xffffffffu, sum, 1);
            sum += __shfl_xor_sync(0xffffffffu, sum, 2);
            l[rr] = l[rr] * sf + sum;
#pragma unroll
            for (int nt = 0; nt < 8; nt++)
#pragma unroll
                for (int cc = 0; cc < 2; cc++) oacc[nt][rr * 2 + cc] *= sf;
        }

        // ---- O += P @ V (P via registers) ----
#pragma unroll
        for (int js = 0; js < 4; js++) {
            uint32_t pa0 = packh2(sacc[2 * js][0], sacc[2 * js][1]);
            uint32_t pa1 = packh2(sacc[2 * js][2], sacc[2 * js][3]);
            uint32_t pa2 = packh2(sacc[2 * js + 1][0], sacc[2 * js + 1][1]);
            uint32_t pa3 = packh2(sacc[2 * js + 1][2], sacc[2 * js + 1][3]);
            uint32_t b[8][2];
#pragma unroll
            for (int np = 0; np < 4; np++)
                ldsm_x4(b[2 * np][0], b[2 * np][1], b[2 * np + 1][0], b[2 * np + 1][1],
                        stV + (np * 16 * AP + js * 8) * 4 + bOff);
#pragma unroll
            for (int nt = 0; nt < 8; nt++)
                MMA_F16(oacc[nt], pa0, pa1, pa2, pa3, b[nt][0], b[nt][1]);
        }
    }

    // ---- normalize + store fp16 to g_attOH[n][t][h*64+e] ----
    const int h = bh & 15;
    float inv0 = 1.0f / l[0];
    float inv1 = 1.0f / l[1];
    int r0 = t0 + rb + gr;
    __half* dst = g_attOH + ((size_t)nb * TQ + r0) * DD + h * DH;
#pragma unroll
    for (int nt = 0; nt < 8; nt++) {
        int col = nt * 8 + 2 * tig;
        *(__half2*)(dst + col) =
            __floats2half2_rn(oacc[nt][0] * inv0, oacc[nt][1] * inv0);
        *(__half2*)(dst + (size_t)8 * DD + col) =
            __floats2half2_rn(oacc[nt][2] * inv1, oacc[nt][3] * inv1);
    }
}

// =========================================================================
extern "C" void kernel_launch(void* const* d_in, const int* in_sizes, int n_in,
                              void* d_out, int out_size) {
    const float* q   = (const float*)d_in[0];
    const float* kv  = (const float*)d_in[1];
    const int*   kvl = (const int*)d_in[2];
    const float* Wq  = (const float*)d_in[3];
    const float* bq  = (const float*)d_in[4];
    const float* Wkv = (const float*)d_in[5];
    const float* bkv = (const float*)d_in[6];
    const float* Wfc = (const float*)d_in[7];
    const float* bfc = (const float*)d_in[8];
    float* out = (float*)d_out;

    cudaFuncSetAttribute(proj_all, cudaFuncAttributeMaxDynamicSharedMemorySize, HGEMM_SMEM);
    cudaFuncSetAttribute(fc_gemm, cudaFuncAttributeMaxDynamicSharedMemorySize, HGEMM_SMEM);
    cudaFuncSetAttribute(attn_h, cudaFuncAttributeMaxDynamicSharedMemorySize, ATTN_SMEM);

    // 1. merged transposes + fused weight convert
    transpose_all<<<dim3(TKK / 32, DD / 32, 2 * NB), 256>>>(q, kv);
    convert_all<<<(DD * DD + 255) / 256, 256>>>(Wq, Wkv, Wfc);

    // 2. merged projections
    proj_all<<<dim3(160, 1, NB), 256, HGEMM_SMEM>>>(bq, bkv);
    // 3. attention (round-13 grid version)
    attn_h<<<dim3(TQ / 128, NB * NH), 256, ATTN_SMEM>>>(kvl);
    // 4. fc
    fc_gemm<<<dim3(DD / 128, TQ / 128, NB), 256, HGEMM_SMEM>>>(bfc, out);
}